// round 4
// baseline (speedup 1.0000x reference)
#include <cuda_runtime.h>
#include <cuda_bf16.h>
#include <cstdint>
#include <cstddef>

// ---------------- problem constants ----------------
#define BATCH   4096
#define UNITS   1024
#define TSTEPS  128
#define BM      128           // batch rows per tile
#define BN      256           // z-cols per tile = 64 units * 4 gates
#define BUN     64            // units per tile
#define KC      64            // K elements per chunk
#define NKC     16            // chunks over K=1024
#define NMT     32            // m tiles
#define NNT     16            // n tiles
#define ROWB    144           // padded smem row: 72 bf16 = 144 bytes
#define STG_A   (BM * ROWB)   // 18432 B
#define STG_B   (BN * ROWB)   // 36864 B
#define O_AH    0
#define O_AL    (STG_A)
#define O_BH    (2 * STG_A)
#define O_BL    (2 * STG_A + STG_B)
#define STAGE   (2 * STG_A + 2 * STG_B)   // 110592 B
#define SMEM_DYN (2 * STAGE)              // 221184 B
#define HN      (4096UL * 1024UL)
#define ZLD     260           // epilogue z smem row stride (floats)

// ---------------- device-global state ----------------
__device__ __nv_bfloat16 g_hh[2][HN];   // hidden hi (ping/pong)  [4096][1024]
__device__ __nv_bfloat16 g_hl[2][HN];   // hidden lo
__device__ __nv_bfloat16 g_Wh[HN * 4];  // permuted W hi: [n=4u+g][k]  (4096x1024)
__device__ __nv_bfloat16 g_Wl[HN * 4];  // permuted W lo
__device__ float         g_c[HN];       // cell state fp32, in place
__device__ float         g_kp[4 * UNITS];   // permuted input kernel
__device__ float         g_bp[4 * UNITS];   // permuted bias
__device__ float         g_x[BATCH];        // autoregressive feedback input

// ---------------- small helpers ----------------
__device__ __forceinline__ uint32_t smem_u32(const void* p) {
    uint32_t a;
    asm("{ .reg .u64 t; cvta.to.shared.u64 t, %1; cvt.u32.u64 %0, t; }" : "=r"(a) : "l"(p));
    return a;
}
__device__ __forceinline__ void cp16(uint32_t dst, const void* src) {
    asm volatile("cp.async.cg.shared.global [%0], [%1], 16;" :: "r"(dst), "l"(src) : "memory");
}
__device__ __forceinline__ void cp_commit() {
    asm volatile("cp.async.commit_group;" ::: "memory");
}
template <int N>
__device__ __forceinline__ void cp_wait() {
    asm volatile("cp.async.wait_group %0;" :: "n"(N) : "memory");
}
__device__ __forceinline__ void ldsm_x4(uint32_t addr, uint32_t* r) {
    asm volatile("ldmatrix.sync.aligned.m8n8.x4.shared.b16 {%0,%1,%2,%3}, [%4];"
                 : "=r"(r[0]), "=r"(r[1]), "=r"(r[2]), "=r"(r[3]) : "r"(addr));
}
__device__ __forceinline__ void mma_bf16(float* d, const uint32_t* a, const uint32_t* b) {
    asm volatile(
        "mma.sync.aligned.m16n8k16.row.col.f32.bf16.bf16.f32 "
        "{%0,%1,%2,%3}, {%4,%5,%6,%7}, {%8,%9}, {%0,%1,%2,%3};"
        : "+f"(d[0]), "+f"(d[1]), "+f"(d[2]), "+f"(d[3])
        : "r"(a[0]), "r"(a[1]), "r"(a[2]), "r"(a[3]), "r"(b[0]), "r"(b[1]));
}
__device__ __forceinline__ float sigf(float x) {
    return __fdividef(1.0f, 1.0f + __expf(-x));
}
__device__ __forceinline__ float tanhf_(float x) {
    return __fdividef(2.0f, 1.0f + __expf(-2.0f * x)) - 1.0f;
}

// ---------------- prep kernels ----------------
// Wt[n=4u+g][k] = split(W[k][g*1024+u]) into bf16 hi/lo
__global__ void prep_w_kernel(const float* __restrict__ W) {
    int u = blockIdx.x * 32 + threadIdx.x;
    int k = blockIdx.y * 8 + threadIdx.y;
    int g = blockIdx.z;
    float v = W[(size_t)k * 4096 + g * 1024 + u];
    __nv_bfloat16 hi = __float2bfloat16(v);
    float lo = v - __bfloat162float(hi);
    size_t o = ((size_t)(4 * u + g)) * 1024 + k;
    g_Wh[o] = hi;
    g_Wl[o] = __float2bfloat16(lo);
}

__global__ void prep_small_kernel(const float* __restrict__ kern, const float* __restrict__ bias) {
    int idx = blockIdx.x * 256 + threadIdx.x;   // 0..4095
    int g = idx & 3, u = idx >> 2;
    int c = g * 1024 + u;
    g_kp[idx] = kern[c];
    g_bp[idx] = bias[c];
    g_x[idx] = 0.0f;
}

__global__ void init_hc_kernel(const float* __restrict__ feat) {
    size_t idx = (size_t)blockIdx.x * 1024 + threadIdx.x;
    int b = blockIdx.x, u = threadIdx.x;
    float v = feat[(size_t)b * 512 + (u & 511)];
    __nv_bfloat16 hi = __float2bfloat16(v);
    float lo = v - __bfloat162float(hi);
    g_hh[0][idx] = hi;
    g_hl[0][idx] = __float2bfloat16(lo);
    g_c[idx] = v;
}

// pred[b] = (h_hi+h_lo)[b,:] . dw + db ; write out[b][t], feedback g_x[b]
__global__ void collect_kernel(const float* __restrict__ dw, const float* __restrict__ db,
                               float* __restrict__ out, int dst, int t) {
    int wid = threadIdx.x >> 5, lid = threadIdx.x & 31;
    int row = blockIdx.x * 8 + wid;
    const __nv_bfloat16* hh = g_hh[dst];
    const __nv_bfloat16* hl = g_hl[dst];
    size_t base = (size_t)row * 1024;
    float s = 0.0f;
    #pragma unroll
    for (int i = 0; i < 32; i++) {
        int u = i * 32 + lid;
        float h = __bfloat162float(hh[base + u]) + __bfloat162float(hl[base + u]);
        s += h * dw[u];
    }
    #pragma unroll
    for (int o = 16; o; o >>= 1) s += __shfl_down_sync(0xFFFFFFFFu, s, o);
    if (lid == 0) {
        float p = s + db[0];
        out[(size_t)row * TSTEPS + t] = p;
        g_x[row] = p;
    }
}

// ---------------- fused LSTM step (mma.sync engine) ----------------
__global__ void __launch_bounds__(256, 1)
step_kernel(int src) {
    extern __shared__ char sm[];
    const int tid = threadIdx.x;
    const int w = tid >> 5, l = tid & 31;
    const int dst = src ^ 1;
    const int mt = blockIdx.x & 31, nt = blockIdx.x >> 5;
    const int m0 = mt << 7;      // batch row base
    const int n0 = nt << 8;      // z col base
    const int u0 = nt << 6;      // unit base

    const __nv_bfloat16* __restrict__ Ah = g_hh[src];
    const __nv_bfloat16* __restrict__ Al = g_hl[src];

    const uint32_t sb = smem_u32(sm);

    // warp tiling: 2 (m) x 4 (n); warp tile 64x64
    const int m_off = (w & 1) * 64;
    const int n_off = (w >> 1) * 64;

    float acc[4][8][4];
    #pragma unroll
    for (int im = 0; im < 4; im++)
        #pragma unroll
        for (int jn = 0; jn < 8; jn++)
            #pragma unroll
            for (int q = 0; q < 4; q++) acc[im][jn][q] = 0.0f;

    // -------- producer: load chunk kc into stage kc&1 --------
    auto load_chunk = [&](int kc) {
        const uint32_t so = sb + (uint32_t)(kc & 1) * STAGE;
        const int k0 = kc * KC;
        #pragma unroll
        for (int i = 0; i < 24; i++) {
            int o = tid + i * 256;   // 0..6143
            if (o < 2048) {          // A hi / lo: 1024 ops each
                int pl = o >> 10;
                int idx = o & 1023;
                int row = idx >> 3, seg = idx & 7;
                uint32_t d = so + (pl ? O_AL : O_AH) + row * ROWB + seg * 16;
                const char* s = (const char*)(pl ? Al : Ah) +
                                ((size_t)(m0 + row) * 1024 + k0) * 2 + seg * 16;
                cp16(d, s);
            } else {                 // B hi / lo: 2048 ops each
                int oo = o - 2048;
                int pl = oo >> 11;
                int idx = oo & 2047;
                int row = idx >> 3, seg = idx & 7;
                uint32_t d = so + (pl ? O_BL : O_BH) + row * ROWB + seg * 16;
                const char* s = (const char*)(pl ? g_Wl : g_Wh) +
                                ((size_t)(n0 + row) * 1024 + k0) * 2 + seg * 16;
                cp16(d, s);
            }
        }
        cp_commit();
    };

    // ldmatrix address helpers (no swizzle; padded rows -> conflict-free)
    auto a_addr = [&](uint32_t base, int im, int ks) -> uint32_t {
        int row = m_off + im * 16 + (l & 15);
        int col = ks * 16 + ((l >> 4) << 3);
        return base + row * ROWB + col * 2;
    };
    auto b_addr = [&](uint32_t base, int jn2, int ks) -> uint32_t {
        int row = n_off + jn2 * 16 + (l & 7) + ((l >> 4) << 3);
        int col = ks * 16 + (((l >> 3) & 1) << 3);
        return base + row * ROWB + col * 2;
    };

    // one sub-pass of one k-step: z += A(plane aoff) * B(plane boff)
    auto subpass = [&](uint32_t so, int aoff, int boff, int ks) {
        uint32_t bb[16];
        #pragma unroll
        for (int jn2 = 0; jn2 < 4; jn2++) ldsm_x4(b_addr(so + boff, jn2, ks), &bb[jn2 * 4]);
        #pragma unroll
        for (int im = 0; im < 4; im++) {
            uint32_t aa[4];
            ldsm_x4(a_addr(so + aoff, im, ks), aa);
            #pragma unroll
            for (int jn = 0; jn < 8; jn++)
                mma_bf16(acc[im][jn], aa, &bb[(jn >> 1) * 4 + (jn & 1) * 2]);
        }
    };

    // -------- pipeline --------
    load_chunk(0);
    load_chunk(1);
    for (int kc = 0; kc < NKC; kc++) {
        cp_wait<1>();
        __syncthreads();
        const uint32_t so = sb + (uint32_t)(kc & 1) * STAGE;
        #pragma unroll
        for (int ks = 0; ks < 4; ks++) {
            subpass(so, O_AH, O_BH, ks);   // hi*hi
            subpass(so, O_AH, O_BL, ks);   // hi*lo
            subpass(so, O_AL, O_BH, ks);   // lo*hi
        }
        __syncthreads();
        if (kc + 2 < NKC) load_chunk(kc + 2);
    }

    // -------- epilogue: acc -> smem z, fuse gates --------
    float* zs = (float*)sm;   // [128][ZLD] fp32 (aliases stage memory)
    #pragma unroll
    for (int im = 0; im < 4; im++) {
        int m = m_off + im * 16 + (l >> 2);
        #pragma unroll
        for (int jn = 0; jn < 8; jn++) {
            int n = n_off + jn * 8 + (l & 3) * 2;
            *(float2*)&zs[m * ZLD + n]       = make_float2(acc[im][jn][0], acc[im][jn][1]);
            *(float2*)&zs[(m + 8) * ZLD + n] = make_float2(acc[im][jn][2], acc[im][jn][3]);
        }
    }
    __syncthreads();

    {
        const int u = tid & 63;        // unit within tile
        const int r0 = tid >> 6;       // 0..3
        const int n = n0 + 4 * u;
        const float4 kp4 = *(const float4*)&g_kp[n];
        const float4 bp4 = *(const float4*)&g_bp[n];
        #pragma unroll 4
        for (int i = 0; i < 32; i++) {
            int r = r0 + 4 * i;
            int row = m0 + r;
            float xr = g_x[row];
            float4 z4 = *(const float4*)&zs[r * ZLD + 4 * u];
            float zi = z4.x + xr * kp4.x + bp4.x;
            float zf = z4.y + xr * kp4.y + bp4.y;
            float zg = z4.z + xr * kp4.z + bp4.z;
            float zo = z4.w + xr * kp4.w + bp4.w;
            size_t gi = (size_t)row * 1024 + u0 + u;
            float co = g_c[gi];
            float iv = sigf(zi), fv = sigf(zf);
            float gv = tanhf_(zg), ov = sigf(zo);
            float cn = fv * co + iv * gv;
            float hn = ov * tanhf_(cn);
            g_c[gi] = cn;
            __nv_bfloat16 hi = __float2bfloat16(hn);
            float lo = hn - __bfloat162float(hi);
            g_hh[dst][gi] = hi;
            g_hl[dst][gi] = __float2bfloat16(lo);
        }
    }
}

// ---------------- host side ----------------
extern "C" void kernel_launch(void* const* d_in, const int* in_sizes, int n_in,
                              void* d_out, int out_size) {
    const float* features = (const float*)d_in[0];
    const float* kern     = (const float*)d_in[1];
    const float* W        = (const float*)d_in[2];
    const float* bias     = (const float*)d_in[3];
    const float* dw       = (const float*)d_in[4];
    const float* db       = (const float*)d_in[5];
    float* out = (float*)d_out;

    cudaFuncSetAttribute(step_kernel, cudaFuncAttributeMaxDynamicSharedMemorySize, SMEM_DYN);

    prep_w_kernel<<<dim3(32, 128, 4), dim3(32, 8)>>>(W);
    prep_small_kernel<<<16, 256>>>(kern, bias);
    init_hc_kernel<<<4096, 1024>>>(features);

    for (int t = 0; t < TSTEPS; t++) {
        int src = t & 1;
        int dst = src ^ 1;
        step_kernel<<<NMT * NNT, 256, SMEM_DYN>>>(src);
        collect_kernel<<<512, 256>>>(dw, db, out, dst, t);
    }
}

// round 5
// speedup vs baseline: 1.0473x; 1.0473x over previous
#include <cuda_runtime.h>
#include <cuda_bf16.h>
#include <cstdint>
#include <cstddef>

// ---------------- problem constants ----------------
#define BATCH   4096
#define UNITS   1024
#define TSTEPS  128
#define BM      128           // batch rows per tile
#define BN      256           // z-cols per tile = 64 units * 4 gates
#define KC      64            // K elements per chunk
#define NKC     16            // chunks over K=1024
#define NMT     32            // m tiles
#define NNT     16            // n tiles
#define ROWB    144           // padded smem row: 72 bf16 = 144 bytes (odd 16B granules -> conflict-free ldsm)
#define STG_A   (BM * ROWB)   // 18432 B
#define STG_B   (BN * ROWB)   // 36864 B
#define O_AH    0
#define O_AL    (STG_A)
#define O_BH    (2 * STG_A)
#define O_BL    (2 * STG_A + STG_B)
#define STAGE   (2 * STG_A + 2 * STG_B)   // 110592 B
#define SMEM_DYN (2 * STAGE)              // 221184 B
#define HN      (4096UL * 1024UL)
#define ZLD     260           // epilogue z smem row stride (floats)

// ---------------- device-global state ----------------
__device__ __nv_bfloat16 g_hh[2][HN];   // hidden hi (ping/pong)  [4096][1024]
__device__ __nv_bfloat16 g_hl[2][HN];   // hidden lo
__device__ __nv_bfloat16 g_Wh[HN * 4];  // permuted W hi: [n=4u+g][k]  (4096x1024)
__device__ __nv_bfloat16 g_Wl[HN * 4];  // permuted W lo
__device__ float         g_c[HN];       // cell state fp32, in place
__device__ float         g_kp[4 * UNITS];   // permuted input kernel
__device__ float         g_bp[4 * UNITS];   // permuted bias
__device__ float         g_x[BATCH];        // autoregressive feedback input

// ---------------- small helpers ----------------
__device__ __forceinline__ uint32_t smem_u32(const void* p) {
    uint32_t a;
    asm("{ .reg .u64 t; cvta.to.shared.u64 t, %1; cvt.u32.u64 %0, t; }" : "=r"(a) : "l"(p));
    return a;
}
__device__ __forceinline__ void cp16(uint32_t dst, const void* src) {
    asm volatile("cp.async.cg.shared.global [%0], [%1], 16;" :: "r"(dst), "l"(src) : "memory");
}
__device__ __forceinline__ void cp_commit() {
    asm volatile("cp.async.commit_group;" ::: "memory");
}
template <int N>
__device__ __forceinline__ void cp_wait() {
    asm volatile("cp.async.wait_group %0;" :: "n"(N) : "memory");
}
__device__ __forceinline__ void ldsm_x4(uint32_t addr, uint32_t* r) {
    asm volatile("ldmatrix.sync.aligned.m8n8.x4.shared.b16 {%0,%1,%2,%3}, [%4];"
                 : "=r"(r[0]), "=r"(r[1]), "=r"(r[2]), "=r"(r[3]) : "r"(addr));
}
__device__ __forceinline__ void mma_bf16(float* d, const uint32_t* a, const uint32_t* b) {
    asm volatile(
        "mma.sync.aligned.m16n8k16.row.col.f32.bf16.bf16.f32 "
        "{%0,%1,%2,%3}, {%4,%5,%6,%7}, {%8,%9}, {%0,%1,%2,%3};"
        : "+f"(d[0]), "+f"(d[1]), "+f"(d[2]), "+f"(d[3])
        : "r"(a[0]), "r"(a[1]), "r"(a[2]), "r"(a[3]), "r"(b[0]), "r"(b[1]));
}
__device__ __forceinline__ float sigf(float x) {
    return __fdividef(1.0f, 1.0f + __expf(-x));
}
__device__ __forceinline__ float tanhf_(float x) {
    return __fdividef(2.0f, 1.0f + __expf(-2.0f * x)) - 1.0f;
}

// ---------------- prep kernels ----------------
__global__ void prep_w_kernel(const float* __restrict__ W) {
    int u = blockIdx.x * 32 + threadIdx.x;
    int k = blockIdx.y * 8 + threadIdx.y;
    int g = blockIdx.z;
    float v = W[(size_t)k * 4096 + g * 1024 + u];
    __nv_bfloat16 hi = __float2bfloat16(v);
    float lo = v - __bfloat162float(hi);
    size_t o = ((size_t)(4 * u + g)) * 1024 + k;
    g_Wh[o] = hi;
    g_Wl[o] = __float2bfloat16(lo);
}

__global__ void prep_small_kernel(const float* __restrict__ kern, const float* __restrict__ bias) {
    int idx = blockIdx.x * 256 + threadIdx.x;   // 0..4095
    int g = idx & 3, u = idx >> 2;
    int c = g * 1024 + u;
    g_kp[idx] = kern[c];
    g_bp[idx] = bias[c];
    g_x[idx] = 0.0f;
}

__global__ void init_hc_kernel(const float* __restrict__ feat) {
    size_t idx = (size_t)blockIdx.x * 1024 + threadIdx.x;
    int b = blockIdx.x, u = threadIdx.x;
    float v = feat[(size_t)b * 512 + (u & 511)];
    __nv_bfloat16 hi = __float2bfloat16(v);
    float lo = v - __bfloat162float(hi);
    g_hh[0][idx] = hi;
    g_hl[0][idx] = __float2bfloat16(lo);
    g_c[idx] = v;
}

// pred[b] = (h_hi+h_lo)[b,:] . dw + db ; write out[b][t], feedback g_x[b]
__global__ void collect_kernel(const float* __restrict__ dw, const float* __restrict__ db,
                               float* __restrict__ out, int dst, int t) {
    int wid = threadIdx.x >> 5, lid = threadIdx.x & 31;
    int row = blockIdx.x * 8 + wid;
    const __nv_bfloat16* hh = g_hh[dst];
    const __nv_bfloat16* hl = g_hl[dst];
    size_t base = (size_t)row * 1024;
    float s = 0.0f;
    #pragma unroll
    for (int i = 0; i < 32; i++) {
        int u = i * 32 + lid;
        float h = __bfloat162float(hh[base + u]) + __bfloat162float(hl[base + u]);
        s += h * dw[u];
    }
    #pragma unroll
    for (int o = 16; o; o >>= 1) s += __shfl_down_sync(0xFFFFFFFFu, s, o);
    if (lid == 0) {
        float p = s + db[0];
        out[(size_t)row * TSTEPS + t] = p;
        g_x[row] = p;
    }
}

// ---------------- fused LSTM step (mma.sync engine, 16 warps) ----------------
__global__ void __launch_bounds__(512, 1)
step_kernel(int src) {
    extern __shared__ char sm[];
    const int tid = threadIdx.x;
    const int w = tid >> 5, l = tid & 31;
    const int dst = src ^ 1;
    const int mt = blockIdx.x & 31, nt = blockIdx.x >> 5;
    const int m0 = mt << 7;      // batch row base
    const int n0 = nt << 8;      // z col base
    const int u0 = nt << 6;      // unit base

    const __nv_bfloat16* __restrict__ Ah = g_hh[src];
    const __nv_bfloat16* __restrict__ Al = g_hl[src];

    const uint32_t sb = smem_u32(sm);

    // warp tiling: 4 (m) x 4 (n); warp tile 32x64
    const int m_off = (w & 3) * 32;
    const int n_off = (w >> 2) * 64;

    float acc[2][8][4];
    #pragma unroll
    for (int im = 0; im < 2; im++)
        #pragma unroll
        for (int jn = 0; jn < 8; jn++)
            #pragma unroll
            for (int q = 0; q < 4; q++) acc[im][jn][q] = 0.0f;

    // -------- producer: load chunk kc into stage kc&1 (6144 x 16B, 12/thread) --------
    auto load_chunk = [&](int kc) {
        const uint32_t so = sb + (uint32_t)(kc & 1) * STAGE;
        const int k0 = kc * KC;
        #pragma unroll
        for (int i = 0; i < 12; i++) {
            int o = tid + i * 512;   // 0..6143
            if (o < 2048) {          // A hi / lo
                int pl = o >> 10;
                int idx = o & 1023;
                int row = idx >> 3, seg = idx & 7;
                uint32_t d = so + (pl ? O_AL : O_AH) + row * ROWB + seg * 16;
                const char* s = (const char*)(pl ? Al : Ah) +
                                ((size_t)(m0 + row) * 1024 + k0) * 2 + seg * 16;
                cp16(d, s);
            } else {                 // B hi / lo
                int oo = o - 2048;
                int pl = oo >> 11;
                int idx = oo & 2047;
                int row = idx >> 3, seg = idx & 7;
                uint32_t d = so + (pl ? O_BL : O_BH) + row * ROWB + seg * 16;
                const char* s = (const char*)(pl ? g_Wl : g_Wh) +
                                ((size_t)(n0 + row) * 1024 + k0) * 2 + seg * 16;
                cp16(d, s);
            }
        }
        cp_commit();
    };

    // ldmatrix address helpers (padded rows -> conflict-free)
    auto a_addr = [&](uint32_t base, int im, int ks) -> uint32_t {
        int row = m_off + im * 16 + (l & 15);
        int col = ks * 16 + ((l >> 4) << 3);
        return base + row * ROWB + col * 2;
    };
    auto b_addr = [&](uint32_t base, int jn2, int ks) -> uint32_t {
        int row = n_off + jn2 * 16 + (l & 7) + ((l >> 4) << 3);
        int col = ks * 16 + (((l >> 3) & 1) << 3);
        return base + row * ROWB + col * 2;
    };

    // -------- pipeline --------
    load_chunk(0);
    load_chunk(1);
    for (int kc = 0; kc < NKC; kc++) {
        cp_wait<1>();
        __syncthreads();
        const uint32_t so = sb + (uint32_t)(kc & 1) * STAGE;
        #pragma unroll
        for (int ks = 0; ks < 4; ks++) {
            uint32_t ah[2][4], al[2][4], bb[16];
            // load A hi/lo fragments once for this k16-step
            #pragma unroll
            for (int im = 0; im < 2; im++) ldsm_x4(a_addr(so + O_AH, im, ks), ah[im]);
            #pragma unroll
            for (int im = 0; im < 2; im++) ldsm_x4(a_addr(so + O_AL, im, ks), al[im]);
            // B_hi fragments
            #pragma unroll
            for (int jn2 = 0; jn2 < 4; jn2++) ldsm_x4(b_addr(so + O_BH, jn2, ks), &bb[jn2 * 4]);
            // hi*hi and lo*hi against resident B_hi
            #pragma unroll
            for (int im = 0; im < 2; im++)
                #pragma unroll
                for (int jn = 0; jn < 8; jn++)
                    mma_bf16(acc[im][jn], ah[im], &bb[(jn >> 1) * 4 + (jn & 1) * 2]);
            #pragma unroll
            for (int im = 0; im < 2; im++)
                #pragma unroll
                for (int jn = 0; jn < 8; jn++)
                    mma_bf16(acc[im][jn], al[im], &bb[(jn >> 1) * 4 + (jn & 1) * 2]);
            // overwrite with B_lo, hi*lo
            #pragma unroll
            for (int jn2 = 0; jn2 < 4; jn2++) ldsm_x4(b_addr(so + O_BL, jn2, ks), &bb[jn2 * 4]);
            #pragma unroll
            for (int im = 0; im < 2; im++)
                #pragma unroll
                for (int jn = 0; jn < 8; jn++)
                    mma_bf16(acc[im][jn], ah[im], &bb[(jn >> 1) * 4 + (jn & 1) * 2]);
        }
        __syncthreads();
        if (kc + 2 < NKC) load_chunk(kc + 2);
    }

    // -------- epilogue: acc -> smem z, fuse gates --------
    float* zs = (float*)sm;   // [128][ZLD] fp32 (aliases stage memory; synced above)
    #pragma unroll
    for (int im = 0; im < 2; im++) {
        int m = m_off + im * 16 + (l >> 2);
        #pragma unroll
        for (int jn = 0; jn < 8; jn++) {
            int n = n_off + jn * 8 + (l & 3) * 2;
            *(float2*)&zs[m * ZLD + n]       = make_float2(acc[im][jn][0], acc[im][jn][1]);
            *(float2*)&zs[(m + 8) * ZLD + n] = make_float2(acc[im][jn][2], acc[im][jn][3]);
        }
    }
    __syncthreads();

    {
        const int u = tid & 63;        // unit within tile
        const int r0 = tid >> 6;       // 0..7
        const int n = n0 + 4 * u;
        const float4 kp4 = *(const float4*)&g_kp[n];
        const float4 bp4 = *(const float4*)&g_bp[n];
        #pragma unroll 4
        for (int i = 0; i < 16; i++) {
            int r = r0 + 8 * i;
            int row = m0 + r;
            float xr = g_x[row];
            float4 z4 = *(const float4*)&zs[r * ZLD + 4 * u];
            float zi = z4.x + xr * kp4.x + bp4.x;
            float zf = z4.y + xr * kp4.y + bp4.y;
            float zg = z4.z + xr * kp4.z + bp4.z;
            float zo = z4.w + xr * kp4.w + bp4.w;
            size_t gi = (size_t)row * 1024 + u0 + u;
            float co = g_c[gi];
            float iv = sigf(zi), fv = sigf(zf);
            float gv = tanhf_(zg), ov = sigf(zo);
            float cn = fv * co + iv * gv;
            float hn = ov * tanhf_(cn);
            g_c[gi] = cn;
            __nv_bfloat16 hi = __float2bfloat16(hn);
            float lo = hn - __bfloat162float(hi);
            g_hh[dst][gi] = hi;
            g_hl[dst][gi] = __float2bfloat16(lo);
        }
    }
}

// ---------------- host side ----------------
extern "C" void kernel_launch(void* const* d_in, const int* in_sizes, int n_in,
                              void* d_out, int out_size) {
    const float* features = (const float*)d_in[0];
    const float* kern     = (const float*)d_in[1];
    const float* W        = (const float*)d_in[2];
    const float* bias     = (const float*)d_in[3];
    const float* dw       = (const float*)d_in[4];
    const float* db       = (const float*)d_in[5];
    float* out = (float*)d_out;

    cudaFuncSetAttribute(step_kernel, cudaFuncAttributeMaxDynamicSharedMemorySize, SMEM_DYN);

    prep_w_kernel<<<dim3(32, 128, 4), dim3(32, 8)>>>(W);
    prep_small_kernel<<<16, 256>>>(kern, bias);
    init_hc_kernel<<<4096, 1024>>>(features);

    for (int t = 0; t < TSTEPS; t++) {
        int src = t & 1;
        int dst = src ^ 1;
        step_kernel<<<NMT * NNT, 512, SMEM_DYN>>>(src);
        collect_kernel<<<512, 256>>>(dw, db, out, dst, t);
    }
}